// round 4
// baseline (speedup 1.0000x reference)
#include <cuda_runtime.h>
#include <math.h>

// e^{u.v} = sum_{a+b+c<=10} u^(a,b,c) v^(a,b,c) / (a!b!c!)   (|u.v|<=1, trunc <3e-8)
// Z_i = sum_f c_f mono_f(u_i) M_f ; W_i = sum_f |f| c_f mono_f(u_i) M_f
// mean H = (1/N) sum_i (log Z_i - W_i/Z_i)  -  N*1e-8
// Two kernels; each ends with an atomic-ticket last-block tail (threadFenceReduction).

#define KDEG   10
#define NF     286
#define NFP    288          // 9*32
#define NGRP   9
#define TPB    128
#define MAXBLK 128

__device__ float    g_Mp[NFP * MAXBLK];  // raw moment partials, TRANSPOSED [feat][blk]
__device__ float2   g_MZW[NFP];          // (c_f*M_f, |f|*c_f*M_f)
__device__ float    g_Hp[MAXBLK];
__device__ unsigned g_t1;                // zero-init at load; reset by last block
__device__ unsigned g_t2;

__device__ __forceinline__ void load_unit(const float* __restrict__ vel, int i,
                                          float& x, float& y, float& z) {
    x = vel[3 * i + 0];
    y = vel[3 * i + 1];
    z = vel[3 * i + 2];
    float nrm = sqrtf(x * x + y * y + z * z);
    float inv = 1.0f / (nrm + 1e-6f);
    x *= inv; y *= inv; z *= inv;
}

// Butterfly compaction: 32 lane-local values -> lane l holds warp-sum of value l.
// 31 shuffles total, 16-way ILP per step.
__device__ __forceinline__ float bfly32(float (&v)[32], int lane) {
#pragma unroll
    for (int m = 16; m >= 1; m >>= 1) {
        bool hi = (lane & m) != 0;
#pragma unroll
        for (int k = 0; k < 16; k++) {
            if (k < m) {
                float keep = hi ? v[k + m] : v[k];
                float send = hi ? v[k] : v[k + m];
                v[k] = keep + __shfl_xor_sync(0xffffffffu, send, m);
            }
        }
    }
    return v[0];
}

// ---------------- K1: per-block moments + last-block fold ----------------
__global__ void __launch_bounds__(TPB)
moments_kernel(const float* __restrict__ vel, int N, int nblk) {
    __shared__ float s4[4][NFP];
    __shared__ int   islast;
    int tid  = threadIdx.x;
    int lane = tid & 31;
    int warp = tid >> 5;

    float acc[NGRP];
#pragma unroll
    for (int g = 0; g < NGRP; g++) acc[g] = 0.f;

    for (int base = blockIdx.x * TPB; base < N; base += nblk * TPB) {
        int i = base + tid;
        float x = 0.f, y = 0.f, z = 0.f, w = 0.f;
        if (i < N) { load_unit(vel, i, x, y, z); w = 1.0f; }

        float px[KDEG + 1], py[KDEG + 1], pz[KDEG + 1];
        px[0] = w; py[0] = 1.0f; pz[0] = 1.0f;      // w masks inactive lanes
#pragma unroll
        for (int d = 1; d <= KDEG; d++) {
            px[d] = px[d - 1] * x;
            py[d] = py[d - 1] * y;
            pz[d] = pz[d - 1] * z;
        }

        float v[32];
        int idx = 0;
#pragma unroll
        for (int a = 0; a <= KDEG; a++) {
#pragma unroll
            for (int b = 0; b <= KDEG - a; b++) {
                float xy = px[a] * py[b];
#pragma unroll
                for (int c = 0; c <= KDEG - a - b; c++) {
                    v[idx & 31] = xy * pz[c];
                    if ((idx & 31) == 31) acc[idx >> 5] += bfly32(v, lane);
                    idx++;
                }
            }
        }
        v[30] = 0.f; v[31] = 0.f;                    // pad group 8 (286 -> 288)
        acc[8] += bfly32(v, lane);
    }

#pragma unroll
    for (int g = 0; g < NGRP; g++) s4[warp][g * 32 + lane] = acc[g];
    __syncthreads();
    for (int f = tid; f < NFP; f += TPB)
        g_Mp[f * MAXBLK + blockIdx.x] = s4[0][f] + s4[1][f] + s4[2][f] + s4[3][f];

    // ---- last-block fold: global reduce + coefficient folding ----
    __threadfence();
    if (tid == 0) islast = (atomicAdd(&g_t1, 1u) == (unsigned)(nblk - 1));
    __syncthreads();
    if (!islast) return;

    for (int f = tid; f < NFP; f += TPB) {
        const float* p = &g_Mp[f * MAXBLK];
        float m = 0.f;
#pragma unroll 8
        for (int b = 0; b < nblk; b++) m += p[b];

        float cf = 0.f, deg = 0.f;
        if (f < NF) {
            int rem = f, ia = 0, ib = 0;
            for (ia = 0; ia <= KDEG; ia++) {
                int cnt = (KDEG + 1 - ia) * (KDEG + 2 - ia) / 2;
                if (rem < cnt) break;
                rem -= cnt;
            }
            for (ib = 0; ib <= KDEG - ia; ib++) {
                int cnt = KDEG + 1 - ia - ib;
                if (rem < cnt) break;
                rem -= cnt;
            }
            int ic = rem;
            float fa = 1.f, fb = 1.f, fc = 1.f;
            for (int t = 2; t <= ia; t++) fa *= (float)t;
            for (int t = 2; t <= ib; t++) fb *= (float)t;
            for (int t = 2; t <= ic; t++) fc *= (float)t;
            cf  = 1.0f / (fa * fb * fc);
            deg = (float)(ia + ib + ic);
        }
        g_MZW[f] = make_float2(cf * m, cf * deg * m);
    }
    if (tid == 0) g_t1 = 0u;     // reset for next graph replay
}

// ---------------- K2: per-point entropy + last-block mean ----------------
__global__ void __launch_bounds__(TPB)
entropy_kernel(const float* __restrict__ vel, float* __restrict__ out,
               int N, int nblk) {
    __shared__ float2 sM[NFP];
    __shared__ float  rs[4];
    __shared__ int    islast;
    int tid  = threadIdx.x;
    int lane = tid & 31;
    int warp = tid >> 5;

    for (int f = tid; f < NFP; f += TPB) sM[f] = g_MZW[f];
    __syncthreads();
    const unsigned long long* sM64 = reinterpret_cast<const unsigned long long*>(sM);

    float H = 0.f;
    for (int base = blockIdx.x * TPB; base < N; base += nblk * TPB) {
        int i = base + tid;
        if (i >= N) break;
        float x, y, z;
        load_unit(vel, i, x, y, z);

        float px[KDEG + 1], py[KDEG + 1], pz[KDEG + 1];
        px[0] = 1.0f; py[0] = 1.0f; pz[0] = 1.0f;
#pragma unroll
        for (int d = 1; d <= KDEG; d++) {
            px[d] = px[d - 1] * x;
            py[d] = py[d - 1] * y;
            pz[d] = pz[d - 1] * z;
        }

        // two packed (Z,W) accumulators -> halve the FMA RAW chain
        unsigned long long accA = 0ull, accB = 0ull;
        int idx = 0;
#pragma unroll
        for (int a = 0; a <= KDEG; a++) {
#pragma unroll
            for (int b = 0; b <= KDEG - a; b++) {
                float xy = px[a] * py[b];
#pragma unroll
                for (int c = 0; c <= KDEG - a - b; c++) {
                    float mono = xy * pz[c];
                    unsigned int mu = __float_as_uint(mono);
                    unsigned long long mm;
                    asm("mov.b64 %0, {%1, %1};" : "=l"(mm) : "r"(mu));
                    if (idx & 1) {
                        asm("fma.rn.f32x2 %0, %1, %2, %3;"
                            : "=l"(accB) : "l"(mm), "l"(sM64[idx]), "l"(accB));
                    } else {
                        asm("fma.rn.f32x2 %0, %1, %2, %3;"
                            : "=l"(accA) : "l"(mm), "l"(sM64[idx]), "l"(accA));
                    }
                    idx++;
                }
            }
        }
        unsigned int za, wa, zb, wb;
        asm("mov.b64 {%0, %1}, %2;" : "=r"(za), "=r"(wa) : "l"(accA));
        asm("mov.b64 {%0, %1}, %2;" : "=r"(zb), "=r"(wb) : "l"(accB));
        float Z = __uint_as_float(za) + __uint_as_float(zb);
        float W = __uint_as_float(wa) + __uint_as_float(wb);
        H += logf(Z) - W / Z;
    }

    H += __shfl_xor_sync(0xffffffffu, H, 16);
    H += __shfl_xor_sync(0xffffffffu, H, 8);
    H += __shfl_xor_sync(0xffffffffu, H, 4);
    H += __shfl_xor_sync(0xffffffffu, H, 2);
    H += __shfl_xor_sync(0xffffffffu, H, 1);
    if (lane == 0) rs[warp] = H;
    __syncthreads();
    if (tid == 0) g_Hp[blockIdx.x] = rs[0] + rs[1] + rs[2] + rs[3];

    // ---- last-block mean ----
    __threadfence();
    if (tid == 0) islast = (atomicAdd(&g_t2, 1u) == (unsigned)(nblk - 1));
    __syncthreads();
    if (!islast) return;

    float a = 0.f;
    for (int b = tid; b < nblk; b += TPB) a += g_Hp[b];
    a += __shfl_xor_sync(0xffffffffu, a, 16);
    a += __shfl_xor_sync(0xffffffffu, a, 8);
    a += __shfl_xor_sync(0xffffffffu, a, 4);
    a += __shfl_xor_sync(0xffffffffu, a, 2);
    a += __shfl_xor_sync(0xffffffffu, a, 1);
    if (lane == 0) rs[warp] = a;
    __syncthreads();
    if (tid == 0) {
        out[0] = (rs[0] + rs[1] + rs[2] + rs[3]) / (float)N - (float)N * 1e-8f;
        g_t2 = 0u;               // reset for next graph replay
    }
}

extern "C" void kernel_launch(void* const* d_in, const int* in_sizes, int n_in,
                              void* d_out, int out_size) {
    const float* vel = (const float*)d_in[0];   // velocities (N,3); positions unused
    int N = in_sizes[0] / 3;
    int nblk = (N + TPB - 1) / TPB;
    if (nblk > MAXBLK) nblk = MAXBLK;
    if (nblk < 1) nblk = 1;

    moments_kernel<<<nblk, TPB>>>(vel, N, nblk);
    entropy_kernel<<<nblk, TPB>>>(vel, (float*)d_out, N, nblk);
}

// round 5
// speedup vs baseline: 3.0800x; 3.0800x over previous
#include <cuda_runtime.h>
#include <math.h>

// e^{u.v} = sum_{a+b+c<=7} u^(a,b,c) v^(a,b,c) / (a!b!c!)   (|u.v|<=1)
//   tail(e^s, deg>7)  <= 2.8e-5 ; tail(s e^s) <= 2.1e-4 -> H abs err ~2e-4 (rel ~2e-5)
// Z_i = sum_f c_f mono_f(u_i) M_f ; W_i = sum_f |f| c_f mono_f(u_i) M_f
// mean H = (1/N) sum_i (log Z_i - W_i/Z_i) - N*1e-8

#define KDEG   7
#define NF     120          // C(10,3)
#define NFP    128          // 4*32
#define NGRP   4
#define TPB    128
#define MAXBLK 128

__device__ float    g_Mp[MAXBLK * NFP];  // per-block raw moment partials [blk][feat]
__device__ float2   g_MZW[NFP];          // (c_f*M_f, |f|*c_f*M_f)
__device__ float    g_Hp[MAXBLK];
__device__ unsigned g_t2;                // zero-init; reset by last block each run

__device__ __forceinline__ void load_unit(const float* __restrict__ vel, int i,
                                          float& x, float& y, float& z) {
    x = vel[3 * i + 0];
    y = vel[3 * i + 1];
    z = vel[3 * i + 2];
    float nrm = sqrtf(x * x + y * y + z * z);
    float inv = 1.0f / (nrm + 1e-6f);
    x *= inv; y *= inv; z *= inv;
}

// Butterfly compaction: 32 lane-local values -> lane l holds warp-sum of value l.
__device__ __forceinline__ float bfly32(float (&v)[32], int lane) {
#pragma unroll
    for (int m = 16; m >= 1; m >>= 1) {
        bool hi = (lane & m) != 0;
#pragma unroll
        for (int k = 0; k < 16; k++) {
            if (k < m) {
                float keep = hi ? v[k + m] : v[k];
                float send = hi ? v[k] : v[k + m];
                v[k] = keep + __shfl_xor_sync(0xffffffffu, send, m);
            }
        }
    }
    return v[0];
}

// ---------------- K1: per-block raw moments (coalesced store, no tail) ----------------
__global__ void __launch_bounds__(TPB)
moments_kernel(const float* __restrict__ vel, int N, int nblk) {
    __shared__ float s4[4][NFP];
    int tid  = threadIdx.x;
    int lane = tid & 31;
    int warp = tid >> 5;

    float acc[NGRP];
#pragma unroll
    for (int g = 0; g < NGRP; g++) acc[g] = 0.f;

    for (int base = blockIdx.x * TPB; base < N; base += nblk * TPB) {
        int i = base + tid;
        float x = 0.f, y = 0.f, z = 0.f, w = 0.f;
        if (i < N) { load_unit(vel, i, x, y, z); w = 1.0f; }

        float px[KDEG + 1], py[KDEG + 1], pz[KDEG + 1];
        px[0] = w; py[0] = 1.0f; pz[0] = 1.0f;      // w masks inactive lanes
#pragma unroll
        for (int d = 1; d <= KDEG; d++) {
            px[d] = px[d - 1] * x;
            py[d] = py[d - 1] * y;
            pz[d] = pz[d - 1] * z;
        }

        float v[32];
        int idx = 0;
#pragma unroll
        for (int a = 0; a <= KDEG; a++) {
#pragma unroll
            for (int b = 0; b <= KDEG - a; b++) {
                float xy = px[a] * py[b];
#pragma unroll
                for (int c = 0; c <= KDEG - a - b; c++) {
                    v[idx & 31] = xy * pz[c];
                    if ((idx & 31) == 31) acc[idx >> 5] += bfly32(v, lane);
                    idx++;
                }
            }
        }
        // idx == 120: pad last group (indices 24..31)
#pragma unroll
        for (int k = 24; k < 32; k++) v[k] = 0.f;
        acc[3] += bfly32(v, lane);
    }

#pragma unroll
    for (int g = 0; g < NGRP; g++) s4[warp][g * 32 + lane] = acc[g];
    __syncthreads();
    // tid covers NFP exactly (128)
    g_Mp[blockIdx.x * NFP + tid] = s4[0][tid] + s4[1][tid] + s4[2][tid] + s4[3][tid];
}

// ---------------- K2: warp-per-feature reduce + coefficient folding ----------------
__global__ void __launch_bounds__(256)
reduce_kernel(int nblk) {
    int f    = (blockIdx.x * blockDim.x + threadIdx.x) >> 5;  // feature
    int lane = threadIdx.x & 31;
    if (f >= NFP) return;

    float acc = 0.f;
    for (int b = lane; b < nblk; b += 32) acc += g_Mp[b * NFP + f];
    acc += __shfl_xor_sync(0xffffffffu, acc, 16);
    acc += __shfl_xor_sync(0xffffffffu, acc, 8);
    acc += __shfl_xor_sync(0xffffffffu, acc, 4);
    acc += __shfl_xor_sync(0xffffffffu, acc, 2);
    acc += __shfl_xor_sync(0xffffffffu, acc, 1);

    if (lane == 0) {
        float cf = 0.f, deg = 0.f;
        if (f < NF) {
            int rem = f, a = 0, b = 0;
            for (a = 0; a <= KDEG; a++) {
                int cnt = (KDEG + 1 - a) * (KDEG + 2 - a) / 2;
                if (rem < cnt) break;
                rem -= cnt;
            }
            for (b = 0; b <= KDEG - a; b++) {
                int cnt = KDEG + 1 - a - b;
                if (rem < cnt) break;
                rem -= cnt;
            }
            int c = rem;
            float fa = 1.f, fb = 1.f, fc = 1.f;
            for (int t = 2; t <= a; t++) fa *= (float)t;
            for (int t = 2; t <= b; t++) fb *= (float)t;
            for (int t = 2; t <= c; t++) fc *= (float)t;
            cf  = 1.0f / (fa * fb * fc);
            deg = (float)(a + b + c);
        }
        g_MZW[f] = make_float2(cf * acc, cf * deg * acc);
    }
}

// ---------------- K3: per-point entropy + last-block mean ----------------
__global__ void __launch_bounds__(TPB)
entropy_kernel(const float* __restrict__ vel, float* __restrict__ out,
               int N, int nblk) {
    __shared__ float2 sM[NFP];
    __shared__ float  rs[4];
    __shared__ int    islast;
    int tid  = threadIdx.x;
    int lane = tid & 31;
    int warp = tid >> 5;

    sM[tid] = g_MZW[tid];
    __syncthreads();
    const unsigned long long* sM64 = reinterpret_cast<const unsigned long long*>(sM);

    float H = 0.f;
    for (int base = blockIdx.x * TPB; base < N; base += nblk * TPB) {
        int i = base + tid;
        if (i >= N) break;
        float x, y, z;
        load_unit(vel, i, x, y, z);

        float px[KDEG + 1], py[KDEG + 1], pz[KDEG + 1];
        px[0] = 1.0f; py[0] = 1.0f; pz[0] = 1.0f;
#pragma unroll
        for (int d = 1; d <= KDEG; d++) {
            px[d] = px[d - 1] * x;
            py[d] = py[d - 1] * y;
            pz[d] = pz[d - 1] * z;
        }

        // two packed (Z,W) accumulators -> halve the FMA RAW chain
        unsigned long long accA = 0ull, accB = 0ull;
        int idx = 0;
#pragma unroll
        for (int a = 0; a <= KDEG; a++) {
#pragma unroll
            for (int b = 0; b <= KDEG - a; b++) {
                float xy = px[a] * py[b];
#pragma unroll
                for (int c = 0; c <= KDEG - a - b; c++) {
                    float mono = xy * pz[c];
                    unsigned int mu = __float_as_uint(mono);
                    unsigned long long mm;
                    asm("mov.b64 %0, {%1, %1};" : "=l"(mm) : "r"(mu));
                    if (idx & 1) {
                        asm("fma.rn.f32x2 %0, %1, %2, %3;"
                            : "=l"(accB) : "l"(mm), "l"(sM64[idx]), "l"(accB));
                    } else {
                        asm("fma.rn.f32x2 %0, %1, %2, %3;"
                            : "=l"(accA) : "l"(mm), "l"(sM64[idx]), "l"(accA));
                    }
                    idx++;
                }
            }
        }
        unsigned int za, wa, zb, wb;
        asm("mov.b64 {%0, %1}, %2;" : "=r"(za), "=r"(wa) : "l"(accA));
        asm("mov.b64 {%0, %1}, %2;" : "=r"(zb), "=r"(wb) : "l"(accB));
        float Z = __uint_as_float(za) + __uint_as_float(zb);
        float W = __uint_as_float(wa) + __uint_as_float(wb);
        H += logf(Z) - W / Z;
    }

    H += __shfl_xor_sync(0xffffffffu, H, 16);
    H += __shfl_xor_sync(0xffffffffu, H, 8);
    H += __shfl_xor_sync(0xffffffffu, H, 4);
    H += __shfl_xor_sync(0xffffffffu, H, 2);
    H += __shfl_xor_sync(0xffffffffu, H, 1);
    if (lane == 0) rs[warp] = H;
    __syncthreads();
    if (tid == 0) g_Hp[blockIdx.x] = rs[0] + rs[1] + rs[2] + rs[3];

    // ---- last-block mean (tiny tail; pattern validated in R4's K2) ----
    __threadfence();
    if (tid == 0) islast = (atomicAdd(&g_t2, 1u) == (unsigned)(nblk - 1));
    __syncthreads();
    if (!islast) return;

    float a = 0.f;
    for (int b = tid; b < nblk; b += TPB) a += g_Hp[b];
    a += __shfl_xor_sync(0xffffffffu, a, 16);
    a += __shfl_xor_sync(0xffffffffu, a, 8);
    a += __shfl_xor_sync(0xffffffffu, a, 4);
    a += __shfl_xor_sync(0xffffffffu, a, 2);
    a += __shfl_xor_sync(0xffffffffu, a, 1);
    if (lane == 0) rs[warp] = a;
    __syncthreads();
    if (tid == 0) {
        out[0] = (rs[0] + rs[1] + rs[2] + rs[3]) / (float)N - (float)N * 1e-8f;
        g_t2 = 0u;               // reset for next graph replay
    }
}

extern "C" void kernel_launch(void* const* d_in, const int* in_sizes, int n_in,
                              void* d_out, int out_size) {
    const float* vel = (const float*)d_in[0];   // velocities (N,3); positions unused
    int N = in_sizes[0] / 3;
    int nblk = (N + TPB - 1) / TPB;
    if (nblk > MAXBLK) nblk = MAXBLK;
    if (nblk < 1) nblk = 1;

    moments_kernel<<<nblk, TPB>>>(vel, N, nblk);
    reduce_kernel<<<(NFP * 32 + 255) / 256, 256>>>(nblk);
    entropy_kernel<<<nblk, TPB>>>(vel, (float*)d_out, N, nblk);
}